// round 4
// baseline (speedup 1.0000x reference)
#include <cuda_runtime.h>
#include <cstdint>
#include <cstddef>

#define TDIM 2048
#define SDIM 2048
#define BSZ  2
#define EDIM 1024
#define NH   16
#define HD   64
#define NZ   (BSZ*NH)          // 32

#define SCALING_F  0.125f      // 64^-0.5
#define D_THRESH_F 3.8918202981106265f   // log(2000/40 - 1) = log(49)

// ---------------- scratch (__device__ globals; no runtime allocs) ------------
__device__ float g_q  [(size_t)NZ * TDIM * HD];     // [z][t][d]
__device__ float g_k  [(size_t)NZ * SDIM * HD];     // [z][s][d]
__device__ float g_v  [(size_t)NZ * SDIM * HD];     // [z][s][d]
__device__ float g_mid[(size_t)TDIM * BSZ * EDIM];  // pre-output-proj attn
__device__ float g_sink[(size_t)TDIM * BSZ * EDIM]; // sink if out lacks attn

// ---------------- helpers ----------------------------------------------------
// round-to-nearest(away) fp32 -> tf32 bit pattern; 2 fixed-lat ALU ops, no CVT
__device__ __forceinline__ uint32_t f2tf32(float x) {
    uint32_t u = __float_as_uint(x);
    return (u + 0x1000u) & 0xFFFFE000u;
}

__device__ __forceinline__ void mma_tf32(float* d, const uint32_t* a, const uint32_t* b) {
    asm volatile(
        "mma.sync.aligned.m16n8k8.row.col.f32.tf32.tf32.f32 "
        "{%0,%1,%2,%3}, {%4,%5,%6,%7}, {%8,%9}, {%0,%1,%2,%3};\n"
        : "+f"(d[0]), "+f"(d[1]), "+f"(d[2]), "+f"(d[3])
        : "r"(a[0]), "r"(a[1]), "r"(a[2]), "r"(a[3]), "r"(b[0]), "r"(b[1]));
}

// ---------------- GEMM: C = X @ W^T + bias, tf32 MMA -------------------------
// X: [M=4096, K=1024] row-major; W: [N=1024, K=1024] row-major.
// mode 0: q  -> (acc+b)*SCALING, store [z][t][64]
// mode 1: k/v -> acc+b,          store [z][s][64]
// mode 2: o  -> acc+b,           store row-major [r][1024]
__global__ __launch_bounds__(256) void gemm_tf32_kernel(
    const float* __restrict__ X, const float* __restrict__ W,
    const float* __restrict__ bias, float* __restrict__ out, int mode)
{
    __shared__ uint32_t As[128][36];   // [m][k], pad 4 -> conflict-free frags
    __shared__ uint32_t Bs[128][36];   // [n][k]

    const int tid  = threadIdx.x;
    const int lane = tid & 31, wid = tid >> 5;
    const int wm = wid >> 2, wn = wid & 3;      // 2 x 4 warp grid, warp tile 64x32
    const int lr = lane >> 2, lc = lane & 3;
    const int rowBase = blockIdx.y * 128;
    const int colBase = blockIdx.x * 128;

    float acc[4][4][4];
    #pragma unroll
    for (int i = 0; i < 4; i++)
        #pragma unroll
        for (int j = 0; j < 4; j++)
            #pragma unroll
            for (int r = 0; r < 4; r++) acc[i][j][r] = 0.f;

    const int ldr = tid >> 1;           // row this thread stages (0..127)
    const int ldc = (tid & 1) * 16;     // 16-float segment
    const float* Ag = X + (size_t)(rowBase + ldr) * EDIM + ldc;
    const float* Bg = W + (size_t)(colBase + ldr) * EDIM + ldc;

    for (int k0 = 0; k0 < EDIM; k0 += 32) {
        __syncthreads();
        #pragma unroll
        for (int i = 0; i < 4; i++) {
            float4 va = *(const float4*)(Ag + k0 + i * 4);
            As[ldr][ldc + i*4 + 0] = f2tf32(va.x);
            As[ldr][ldc + i*4 + 1] = f2tf32(va.y);
            As[ldr][ldc + i*4 + 2] = f2tf32(va.z);
            As[ldr][ldc + i*4 + 3] = f2tf32(va.w);
            float4 vb = *(const float4*)(Bg + k0 + i * 4);
            Bs[ldr][ldc + i*4 + 0] = f2tf32(vb.x);
            Bs[ldr][ldc + i*4 + 1] = f2tf32(vb.y);
            Bs[ldr][ldc + i*4 + 2] = f2tf32(vb.z);
            Bs[ldr][ldc + i*4 + 3] = f2tf32(vb.w);
        }
        __syncthreads();
        #pragma unroll
        for (int kk = 0; kk < 4; kk++) {
            const int ko = kk * 8;
            uint32_t a[4][4], b[4][2];
            #pragma unroll
            for (int mf = 0; mf < 4; mf++) {
                int m = wm * 64 + mf * 16;
                // PTX tf32 m16n8k8 A-frag order: (g,c) (g+8,c) (g,c+4) (g+8,c+4)
                a[mf][0] = As[m + lr    ][ko + lc    ];
                a[mf][1] = As[m + lr + 8][ko + lc    ];
                a[mf][2] = As[m + lr    ][ko + lc + 4];
                a[mf][3] = As[m + lr + 8][ko + lc + 4];
            }
            #pragma unroll
            for (int nf = 0; nf < 4; nf++) {
                int n = wn * 32 + nf * 8;
                b[nf][0] = Bs[n + lr][ko + lc    ];
                b[nf][1] = Bs[n + lr][ko + lc + 4];
            }
            #pragma unroll
            for (int mf = 0; mf < 4; mf++)
                #pragma unroll
                for (int nf = 0; nf < 4; nf++)
                    mma_tf32(acc[mf][nf], a[mf], b[nf]);
        }
    }

    // epilogue
    #pragma unroll
    for (int mf = 0; mf < 4; mf++) {
        #pragma unroll
        for (int nf = 0; nf < 4; nf++) {
            #pragma unroll
            for (int r = 0; r < 4; r++) {
                int row = rowBase + wm * 64 + mf * 16 + lr + ((r >> 1) << 3);
                int col = colBase + wn * 32 + nf * 8 + 2 * lc + (r & 1);
                float v = acc[mf][nf][r] + bias[col];
                if (mode == 0) v *= SCALING_F;
                if (mode <= 1) {
                    int t = row >> 1, bb = row & 1;          // row = t*B + b
                    int z = bb * NH + (col >> 6);            // z = b*H + h
                    out[((size_t)(z * TDIM + t) << 6) + (col & 63)] = v;
                } else {
                    out[(size_t)row * EDIM + col] = v;
                }
            }
        }
    }
}

// ---------------- fused attention kernel -------------------------------------
// Per CTA: one z, 16 consecutive t-rows. Scores for the full S=2048 kept in SMEM.
#define SC_STRIDE 2052      // 2048 + 4 floats -> conflict-free frag reads
#define KV_STRIDE 72        // 64 + 8 uints    -> conflict-free frag reads
#define ATTN_SMEM (16*SC_STRIDE*4 + 128*KV_STRIDE*4 + (128+16+16)*4)

__global__ __launch_bounds__(256) void attn_kernel(
    const float* __restrict__ qs, const float* __restrict__ ks,
    const float* __restrict__ vs, const int* __restrict__ mask,
    float* __restrict__ wout, float* __restrict__ attn_mid, int write_w)
{
    extern __shared__ char smraw[];
    float*    sc     = (float*)smraw;                                    // [16][2052]
    uint32_t* kv     = (uint32_t*)(smraw + 16 * SC_STRIDE * 4);          // [128][72]
    float*    red    = (float*)(smraw + 16*SC_STRIDE*4 + 128*KV_STRIDE*4); // [8][16]
    float*    rowmax = red + 128;                                        // [16]
    float*    rinvs  = rowmax + 16;                                      // [16]

    const int tid = threadIdx.x, lane = tid & 31, w = tid >> 5;
    const int lr = lane >> 2, lc = lane & 3;
    const int t0 = blockIdx.x * 16;
    const int z  = blockIdx.y;
    const float NEG = __int_as_float(0xff800000);

    // preload q fragments (16 rows x 64) into registers, tf32-rounded
    // PTX tf32 m16n8k8 A-frag order: (g,c) (g+8,c) (g,c+4) (g+8,c+4)
    uint32_t aq[8][4];
    {
        const float* qg = qs + ((size_t)(z * TDIM + t0)) * HD;
        #pragma unroll
        for (int kk = 0; kk < 8; kk++) {
            aq[kk][0] = f2tf32(qg[ lr      * 64 + kk*8 + lc    ]);
            aq[kk][1] = f2tf32(qg[(lr + 8) * 64 + kk*8 + lc    ]);
            aq[kk][2] = f2tf32(qg[ lr      * 64 + kk*8 + lc + 4]);
            aq[kk][3] = f2tf32(qg[(lr + 8) * 64 + kk*8 + lc + 4]);
        }
    }

    // ---------------- phase 1: scores + row max ----------------
    float mx0 = NEG, mx1 = NEG;
    const float* kbase = ks + (size_t)z * SDIM * HD;
    for (int s0 = 0; s0 < SDIM; s0 += 128) {
        __syncthreads();
        #pragma unroll
        for (int i = 0; i < 8; i++) {            // 128x64 k-chunk -> SMEM (tf32)
            int idx = tid + i * 256;             // float4 index 0..2047
            int row = idx >> 4, c4 = (idx & 15) * 4;
            float4 vq = *(const float4*)(kbase + (size_t)(s0 + row) * 64 + c4);
            kv[row * KV_STRIDE + c4 + 0] = f2tf32(vq.x);
            kv[row * KV_STRIDE + c4 + 1] = f2tf32(vq.y);
            kv[row * KV_STRIDE + c4 + 2] = f2tf32(vq.z);
            kv[row * KV_STRIDE + c4 + 3] = f2tf32(vq.w);
        }
        __syncthreads();

        float c[2][4] = {{0.f,0.f,0.f,0.f},{0.f,0.f,0.f,0.f}};
        #pragma unroll
        for (int kk = 0; kk < 8; kk++) {
            #pragma unroll
            for (int nf = 0; nf < 2; nf++) {
                int n = w * 16 + nf * 8;
                uint32_t b[2];
                b[0] = kv[(n + lr) * KV_STRIDE + kk*8 + lc    ];
                b[1] = kv[(n + lr) * KV_STRIDE + kk*8 + lc + 4];
                mma_tf32(c[nf], aq[kk], b);
            }
        }
        #pragma unroll
        for (int nf = 0; nf < 2; nf++) {
            #pragma unroll
            for (int r = 0; r < 4; r++) {
                int row = lr + ((r >> 1) << 3);
                int col = s0 + w * 16 + nf * 8 + 2 * lc + (r & 1);
                float v = c[nf][r];
                if (mask[(size_t)(t0 + row) * SDIM + col] == 0) v = NEG;
                sc[row * SC_STRIDE + col] = v;
                if (r < 2) mx0 = fmaxf(mx0, v); else mx1 = fmaxf(mx1, v);
            }
        }
    }

    // row-max reduction
    mx0 = fmaxf(mx0, __shfl_xor_sync(0xffffffffu, mx0, 1));
    mx0 = fmaxf(mx0, __shfl_xor_sync(0xffffffffu, mx0, 2));
    mx1 = fmaxf(mx1, __shfl_xor_sync(0xffffffffu, mx1, 1));
    mx1 = fmaxf(mx1, __shfl_xor_sync(0xffffffffu, mx1, 2));
    if (lc == 0) { red[w * 16 + lr] = mx0; red[w * 16 + lr + 8] = mx1; }
    __syncthreads();
    if (tid < 16) {
        float m = red[tid];
        #pragma unroll
        for (int i = 1; i < 8; i++) m = fmaxf(m, red[i * 16 + tid]);
        rowmax[tid] = m;
    }
    __syncthreads();

    // ---------------- phase 2: exp/threshold + rowsum + write weights --------
    #pragma unroll
    for (int rr = 0; rr < 2; rr++) {
        int row = w * 2 + rr;
        float m = rowmax[row];
        float sum = 0.f;
        for (int col = lane; col < SDIM; col += 32) {
            float s = sc[row * SC_STRIDE + col];
            float d = s - m;                               // NaN if both -inf
            float e = (d >= -D_THRESH_F) ? __expf(d) : 0.f;
            sc[row * SC_STRIDE + col] = e;
            sum += e;
        }
        #pragma unroll
        for (int off = 16; off; off >>= 1)
            sum += __shfl_xor_sync(0xffffffffu, sum, off);
        float ri = 1.f / sum;
        if (lane == 0) rinvs[row] = ri;
        if (write_w) {
            float* wo = wout + ((size_t)z * TDIM + (t0 + row)) * SDIM;
            for (int col = lane; col < SDIM; col += 32)
                wo[col] = sc[row * SC_STRIDE + col] * ri;
        }
    }

    // ---------------- phase 3: AV = p @ v ----------------
    float acc[4] = {0.f, 0.f, 0.f, 0.f};
    const float* vbase = vs + (size_t)z * SDIM * HD;
    for (int s0 = 0; s0 < SDIM; s0 += 128) {
        __syncthreads();                        // also orders phase-2 sc writes
        #pragma unroll
        for (int i = 0; i < 8; i++) {
            int idx = tid + i * 256;
            int row = idx >> 4, c4 = (idx & 15) * 4;
            float4 vq = *(const float4*)(vbase + (size_t)(s0 + row) * 64 + c4);
            kv[row * KV_STRIDE + c4 + 0] = f2tf32(vq.x);
            kv[row * KV_STRIDE + c4 + 1] = f2tf32(vq.y);
            kv[row * KV_STRIDE + c4 + 2] = f2tf32(vq.z);
            kv[row * KV_STRIDE + c4 + 3] = f2tf32(vq.w);
        }
        __syncthreads();
        #pragma unroll
        for (int kk = 0; kk < 16; kk++) {
            int kg = s0 + kk * 8;
            uint32_t a[4], b[2];
            // PTX tf32 m16n8k8 A-frag order: (g,c) (g+8,c) (g,c+4) (g+8,c+4)
            a[0] = f2tf32(sc[ lr      * SC_STRIDE + kg + lc    ]);
            a[1] = f2tf32(sc[(lr + 8) * SC_STRIDE + kg + lc    ]);
            a[2] = f2tf32(sc[ lr      * SC_STRIDE + kg + lc + 4]);
            a[3] = f2tf32(sc[(lr + 8) * SC_STRIDE + kg + lc + 4]);
            b[0] = kv[(kk*8 + lc    ) * KV_STRIDE + w * 8 + lr];
            b[1] = kv[(kk*8 + lc + 4) * KV_STRIDE + w * 8 + lr];
            mma_tf32(acc, a, b);
        }
    }

    // epilogue: scale by 1/rowsum, scatter into [t][b][h*64+d]
    #pragma unroll
    for (int r = 0; r < 4; r++) {
        int row  = lr + ((r >> 1) << 3);
        int colh = w * 8 + 2 * lc + (r & 1);
        float v = acc[r] * rinvs[row];
        int t = t0 + row;
        int bb = z >> 4, hh = z & 15;
        attn_mid[((size_t)(t * BSZ + bb)) * EDIM + hh * 64 + colh] = v;
    }
}

// ---------------- launcher ----------------------------------------------------
extern "C" void kernel_launch(void* const* d_in, const int* in_sizes, int n_in,
                              void* d_out, int out_size) {
    const float* query = (const float*)d_in[0];
    const float* key   = (const float*)d_in[1];
    const float* value = (const float*)d_in[2];
    const int*   mask  = (const int*)  d_in[3];
    const float* Wq = (const float*)d_in[4];
    const float* bq = (const float*)d_in[5];
    const float* Wk = (const float*)d_in[6];
    const float* bk = (const float*)d_in[7];
    const float* Wv = (const float*)d_in[8];
    const float* bv = (const float*)d_in[9];
    const float* Wo = (const float*)d_in[10];
    const float* bo = (const float*)d_in[11];

    float *pq, *pk, *pv, *pmid, *psink;
    cudaGetSymbolAddress((void**)&pq,   g_q);
    cudaGetSymbolAddress((void**)&pk,   g_k);
    cudaGetSymbolAddress((void**)&pv,   g_v);
    cudaGetSymbolAddress((void**)&pmid, g_mid);
    cudaGetSymbolAddress((void**)&psink, g_sink);

    const long long ATTN_N = (long long)TDIM * BSZ * EDIM;       // 4,194,304
    const long long WTS_N  = (long long)NZ * TDIM * SDIM;        // 134,217,728
    float* out = (float*)d_out;
    float* out_attn = out;
    float* out_w    = nullptr;
    int write_w = 0;
    long long osz = (long long)out_size;
    if (osz >= ATTN_N + WTS_N)      { out_attn = out; out_w = out + ATTN_N; write_w = 1; }
    else if (osz == WTS_N)          { out_attn = psink; out_w = out; write_w = 1; }
    else                            { out_attn = out; write_w = 0; out_w = psink; }

    dim3 gg(EDIM / 128, (TDIM * BSZ) / 128);   // (8, 32)
    gemm_tf32_kernel<<<gg, 256>>>(query, Wq, bq, pq, 0);
    gemm_tf32_kernel<<<gg, 256>>>(key,   Wk, bk, pk, 1);
    gemm_tf32_kernel<<<gg, 256>>>(value, Wv, bv, pv, 1);

    cudaFuncSetAttribute(attn_kernel,
                         cudaFuncAttributeMaxDynamicSharedMemorySize, ATTN_SMEM);
    attn_kernel<<<dim3(TDIM / 16, NZ), 256, ATTN_SMEM>>>(
        pq, pk, pv, mask, out_w, pmid, write_w);

    gemm_tf32_kernel<<<gg, 256>>>(pmid, Wo, bo, out_attn, 2);
}

// round 5
// speedup vs baseline: 1.6684x; 1.6684x over previous
#include <cuda_runtime.h>
#include <cstdint>
#include <cstddef>

#define TDIM 2048
#define SDIM 2048
#define BSZ  2
#define EDIM 1024
#define NH   16
#define HD   64
#define NZ   (BSZ*NH)          // 32

#define SCALING_F  0.125f      // 64^-0.5
#define D_THRESH_F 3.8918202981106265f   // log(2000/40 - 1) = log(49)

// ---------------- scratch (__device__ globals; no runtime allocs) ------------
__device__ float g_q  [(size_t)NZ * TDIM * HD];     // [z][t][d]
__device__ float g_k  [(size_t)NZ * SDIM * HD];     // [z][s][d]
__device__ float g_v  [(size_t)NZ * SDIM * HD];     // [z][s][d]
__device__ float g_mid[(size_t)TDIM * BSZ * EDIM];  // pre-output-proj attn
__device__ float g_sink[(size_t)TDIM * BSZ * EDIM]; // sink if out lacks attn

// ---------------- helpers ----------------------------------------------------
__device__ __forceinline__ uint32_t f2tf32(float x) {   // RN fp32->tf32 bits
    uint32_t u = __float_as_uint(x);
    return (u + 0x1000u) & 0xFFFFE000u;
}

__device__ __forceinline__ void mma_tf32(float* d, const uint32_t* a, const uint32_t* b) {
    asm volatile(
        "mma.sync.aligned.m16n8k8.row.col.f32.tf32.tf32.f32 "
        "{%0,%1,%2,%3}, {%4,%5,%6,%7}, {%8,%9}, {%0,%1,%2,%3};\n"
        : "+f"(d[0]), "+f"(d[1]), "+f"(d[2]), "+f"(d[3])
        : "r"(a[0]), "r"(a[1]), "r"(a[2]), "r"(a[3]), "r"(b[0]), "r"(b[1]));
}

__device__ __forceinline__ uint32_t s2u(const void* p) {
    return (uint32_t)__cvta_generic_to_shared(p);
}
__device__ __forceinline__ void cpa16(uint32_t dst, const void* src) {
    asm volatile("cp.async.cg.shared.global [%0], [%1], 16;\n" :: "r"(dst), "l"(src) : "memory");
}
#define CPA_COMMIT() asm volatile("cp.async.commit_group;\n" ::: "memory")
#define CPA_WAIT0()  asm volatile("cp.async.wait_group 0;\n" ::: "memory")
#define CPA_WAIT1()  asm volatile("cp.async.wait_group 1;\n" ::: "memory")

// ---------------- GEMM: C = X @ W^T + bias, tf32 MMA, cp.async dbl-buffer ----
// X: [4096,1024] rm; W: [1024,1024] rm. mode 0: q scaled/scatter; 1: k/v scatter;
// 2: row-major out.
#define GS 36                                 // padded k-stride (floats)
#define GEMM_SMEM (4 * 128 * GS * 4)          // As[2]+Bs[2] = 73728 B

__global__ __launch_bounds__(256, 2) void gemm_tf32_kernel(
    const float* __restrict__ X, const float* __restrict__ W,
    const float* __restrict__ bias, float* __restrict__ out, int mode)
{
    extern __shared__ float gsm[];
    float* As = gsm;                  // [2][128][GS]
    float* Bs = gsm + 2 * 128 * GS;   // [2][128][GS]

    const int tid  = threadIdx.x;
    const int lane = tid & 31, wid = tid >> 5;
    const int wm = wid >> 2, wn = wid & 3;      // 2 x 4 warp grid, 64x32 warp tile
    const int lr = lane >> 2, lc = lane & 3;
    const int rowBase = blockIdx.y * 128;
    const int colBase = blockIdx.x * 128;

    float acc[4][4][4];
    #pragma unroll
    for (int i = 0; i < 4; i++)
        #pragma unroll
        for (int j = 0; j < 4; j++)
            #pragma unroll
            for (int r = 0; r < 4; r++) acc[i][j][r] = 0.f;

    const float* Ag = X + (size_t)rowBase * EDIM;
    const float* Bg = W + (size_t)colBase * EDIM;

    // stage one 128x32 chunk of A and B into buffer `buf` (raw fp32)
    auto stage = [&](int k0, int buf) {
        #pragma unroll
        for (int i = 0; i < 4; i++) {
            int idx = tid + i * 256;          // float4 id 0..1023
            int row = idx >> 3, c4 = (idx & 7) * 4;
            cpa16(s2u(&As[(buf * 128 + row) * GS + c4]),
                  Ag + (size_t)row * EDIM + k0 + c4);
            cpa16(s2u(&Bs[(buf * 128 + row) * GS + c4]),
                  Bg + (size_t)row * EDIM + k0 + c4);
        }
        CPA_COMMIT();
    };

    stage(0, 0);
    for (int c = 0; c < 32; c++) {
        __syncthreads();
        if (c < 31) { stage((c + 1) * 32, (c + 1) & 1); CPA_WAIT1(); }
        else        { CPA_WAIT0(); }
        __syncthreads();
        const float* Ab = As + (c & 1) * 128 * GS;
        const float* Bb = Bs + (c & 1) * 128 * GS;
        #pragma unroll
        for (int kk = 0; kk < 4; kk++) {
            const int ko = kk * 8;
            uint32_t a[4][4], b[4][2];
            #pragma unroll
            for (int mf = 0; mf < 4; mf++) {
                int m = wm * 64 + mf * 16;
                // tf32 m16n8k8 A order: (g,c) (g+8,c) (g,c+4) (g+8,c+4)
                a[mf][0] = f2tf32(Ab[(m + lr    ) * GS + ko + lc    ]);
                a[mf][1] = f2tf32(Ab[(m + lr + 8) * GS + ko + lc    ]);
                a[mf][2] = f2tf32(Ab[(m + lr    ) * GS + ko + lc + 4]);
                a[mf][3] = f2tf32(Ab[(m + lr + 8) * GS + ko + lc + 4]);
            }
            #pragma unroll
            for (int nf = 0; nf < 4; nf++) {
                int n = wn * 32 + nf * 8;
                b[nf][0] = f2tf32(Bb[(n + lr) * GS + ko + lc    ]);
                b[nf][1] = f2tf32(Bb[(n + lr) * GS + ko + lc + 4]);
            }
            #pragma unroll
            for (int mf = 0; mf < 4; mf++)
                #pragma unroll
                for (int nf = 0; nf < 4; nf++)
                    mma_tf32(acc[mf][nf], a[mf], b[nf]);
        }
    }

    // epilogue (float2 stores: r pairs are adjacent columns)
    #pragma unroll
    for (int mf = 0; mf < 4; mf++) {
        #pragma unroll
        for (int nf = 0; nf < 4; nf++) {
            #pragma unroll
            for (int rp = 0; rp < 2; rp++) {
                int row = rowBase + wm * 64 + mf * 16 + lr + rp * 8;
                int col = colBase + wn * 32 + nf * 8 + 2 * lc;
                float v0 = acc[mf][nf][rp * 2 + 0] + bias[col];
                float v1 = acc[mf][nf][rp * 2 + 1] + bias[col + 1];
                if (mode == 0) { v0 *= SCALING_F; v1 *= SCALING_F; }
                if (mode <= 1) {
                    int t = row >> 1, bb = row & 1;          // row = t*B + b
                    int z = bb * NH + (col >> 6);            // z = b*H + h
                    *(float2*)&out[((size_t)(z * TDIM + t) << 6) + (col & 63)]
                        = make_float2(v0, v1);
                } else {
                    *(float2*)&out[(size_t)row * EDIM + col] = make_float2(v0, v1);
                }
            }
        }
    }
}

// ---------------- fused attention kernel -------------------------------------
// Per CTA: one z, 16 t-rows, 512 threads (16 warps). Scores [16][2048] in SMEM.
// K/V staged raw-fp32 via cp.async double buffer; tf32 conversion at frag load.
#define SC_STRIDE 2052      // 2048 + 4 -> conflict-free frag reads (2052%32==4)
#define KV_STRIDE 72        // 64 + 8   -> conflict-free (72%32==8)
#define SC_FLOATS (16 * SC_STRIDE)
#define KV_FLOATS (2 * 128 * KV_STRIDE)
#define ATTN_SMEM ((SC_FLOATS + KV_FLOATS + 1024 + 256 + 16 + 16) * 4)

__global__ __launch_bounds__(512, 1) void attn_kernel(
    const float* __restrict__ qs, const float* __restrict__ ks,
    const float* __restrict__ vs, const int* __restrict__ mask,
    float* __restrict__ wout, float* __restrict__ attn_mid, int write_w)
{
    extern __shared__ float sm[];
    float* sc     = sm;                         // [16][SC_STRIDE]
    float* kvb    = sm + SC_FLOATS;             // [2][128][KV_STRIDE] raw fp32
    float* pacc   = kvb + KV_FLOATS;            // [8][128] phase-3 partials
    float* red    = pacc + 1024;                // [16][16] rowmax partials
    float* rowmax = red + 256;                  // [16]
    float* rinvs  = rowmax + 16;                // [16]

    const int tid = threadIdx.x, lane = tid & 31, w = tid >> 5;   // w: 0..15
    const int lr = lane >> 2, lc = lane & 3;
    const int t0 = blockIdx.x * 16;
    const int z  = blockIdx.y;
    const float NEG = __int_as_float(0xff800000);

    // q fragments: 16 rows x 64, tf32-rounded, registers
    uint32_t aq[8][4];
    {
        const float* qg = qs + ((size_t)(z * TDIM + t0)) * HD;
        #pragma unroll
        for (int kk = 0; kk < 8; kk++) {
            aq[kk][0] = f2tf32(qg[ lr      * 64 + kk*8 + lc    ]);
            aq[kk][1] = f2tf32(qg[(lr + 8) * 64 + kk*8 + lc    ]);
            aq[kk][2] = f2tf32(qg[ lr      * 64 + kk*8 + lc + 4]);
            aq[kk][3] = f2tf32(qg[(lr + 8) * 64 + kk*8 + lc + 4]);
        }
    }

    // stage one 128x64 fp32 chunk of `src` into kv buffer `buf`
    auto stageKV = [&](const float* src, int s0, int buf) {
        #pragma unroll
        for (int i = 0; i < 4; i++) {
            int idx = tid + i * 512;              // float4 id 0..2047
            int row = idx >> 4, c4 = (idx & 15) * 4;
            cpa16(s2u(&kvb[(buf * 128 + row) * KV_STRIDE + c4]),
                  src + (size_t)(s0 + row) * HD + c4);
        }
        CPA_COMMIT();
    };

    // ---------------- phase 1: scores + row max ----------------
    float mx0 = NEG, mx1 = NEG;
    const float* kbase = ks + (size_t)z * SDIM * HD;
    stageKV(kbase, 0, 0);
    for (int c = 0; c < 16; c++) {
        const int s0 = c * 128;
        __syncthreads();
        if (c < 15) { stageKV(kbase, s0 + 128, (c + 1) & 1); CPA_WAIT1(); }
        else        { CPA_WAIT0(); }
        __syncthreads();

        // mask prefetch (adjacent columns -> int2)
        const int col0 = s0 + w * 8 + 2 * lc;
        int2 m0 = *(const int2*)(mask + (size_t)(t0 + lr    ) * SDIM + col0);
        int2 m1 = *(const int2*)(mask + (size_t)(t0 + lr + 8) * SDIM + col0);

        const float* kb = kvb + (c & 1) * 128 * KV_STRIDE;
        float cacc[4] = {0.f, 0.f, 0.f, 0.f};
        #pragma unroll
        for (int kk = 0; kk < 8; kk++) {
            uint32_t b[2];
            b[0] = f2tf32(kb[(w * 8 + lr) * KV_STRIDE + kk*8 + lc    ]);
            b[1] = f2tf32(kb[(w * 8 + lr) * KV_STRIDE + kk*8 + lc + 4]);
            mma_tf32(cacc, aq[kk], b);
        }
        float v0 = (m0.x == 0) ? NEG : cacc[0];
        float v1 = (m0.y == 0) ? NEG : cacc[1];
        float v2 = (m1.x == 0) ? NEG : cacc[2];
        float v3 = (m1.y == 0) ? NEG : cacc[3];
        *(float2*)&sc[ lr      * SC_STRIDE + col0] = make_float2(v0, v1);
        *(float2*)&sc[(lr + 8) * SC_STRIDE + col0] = make_float2(v2, v3);
        mx0 = fmaxf(mx0, fmaxf(v0, v1));
        mx1 = fmaxf(mx1, fmaxf(v2, v3));
    }

    // row-max reduction (each warp covered cols ≡ its octet mod 128, all chunks)
    mx0 = fmaxf(mx0, __shfl_xor_sync(0xffffffffu, mx0, 1));
    mx0 = fmaxf(mx0, __shfl_xor_sync(0xffffffffu, mx0, 2));
    mx1 = fmaxf(mx1, __shfl_xor_sync(0xffffffffu, mx1, 1));
    mx1 = fmaxf(mx1, __shfl_xor_sync(0xffffffffu, mx1, 2));
    if (lc == 0) { red[w * 16 + lr] = mx0; red[w * 16 + lr + 8] = mx1; }
    __syncthreads();
    if (tid < 16) {
        float m = red[tid];
        #pragma unroll
        for (int i = 1; i < 16; i++) m = fmaxf(m, red[i * 16 + tid]);
        rowmax[tid] = m;
    }
    __syncthreads();

    // ---------------- phase 2: exp/threshold + rowsum + weights (warp=row) ---
    {
        const int row = w;
        const float m = rowmax[row];
        float sum = 0.f;
        #pragma unroll 4
        for (int col = lane; col < SDIM; col += 32) {
            float s = sc[row * SC_STRIDE + col];
            float d = s - m;
            float e = (d >= -D_THRESH_F) ? __expf(d) : 0.f;
            sc[row * SC_STRIDE + col] = e;
            sum += e;
        }
        #pragma unroll
        for (int off = 16; off; off >>= 1)
            sum += __shfl_xor_sync(0xffffffffu, sum, off);
        float ri = 1.f / sum;
        if (lane == 0) rinvs[row] = ri;
        if (write_w) {
            float* wo = wout + ((size_t)z * TDIM + (t0 + row)) * SDIM;
            #pragma unroll 4
            for (int col = lane; col < SDIM; col += 32)
                wo[col] = sc[row * SC_STRIDE + col] * ri;
        }
    }

    // ---------------- phase 3: AV = p @ v (n split 8 octets, k split 2) ------
    const int nOct  = w & 7;
    const int kHalf = w >> 3;
    float acc[4] = {0.f, 0.f, 0.f, 0.f};
    const float* vbase = vs + (size_t)z * SDIM * HD;
    stageKV(vbase, 0, 0);
    for (int c = 0; c < 16; c++) {
        const int s0 = c * 128;
        __syncthreads();                         // also orders phase-2 sc writes
        if (c < 15) { stageKV(vbase, s0 + 128, (c + 1) & 1); CPA_WAIT1(); }
        else        { CPA_WAIT0(); }
        __syncthreads();
        const float* vb = kvb + (c & 1) * 128 * KV_STRIDE;
        #pragma unroll
        for (int j = 0; j < 8; j++) {
            const int kk = kHalf * 8 + j;
            const int kg = s0 + kk * 8;
            uint32_t a[4], b[2];
            a[0] = f2tf32(sc[ lr      * SC_STRIDE + kg + lc    ]);
            a[1] = f2tf32(sc[(lr + 8) * SC_STRIDE + kg + lc    ]);
            a[2] = f2tf32(sc[ lr      * SC_STRIDE + kg + lc + 4]);
            a[3] = f2tf32(sc[(lr + 8) * SC_STRIDE + kg + lc + 4]);
            b[0] = f2tf32(vb[(kk*8 + lc    ) * KV_STRIDE + nOct * 8 + lr]);
            b[1] = f2tf32(vb[(kk*8 + lc + 4) * KV_STRIDE + nOct * 8 + lr]);
            mma_tf32(acc, a, b);
        }
    }

    // combine k-halves: warps 8-15 park partials, warps 0-7 add + store
    if (kHalf == 1) {
        #pragma unroll
        for (int r = 0; r < 4; r++) pacc[nOct * 128 + lane * 4 + r] = acc[r];
    }
    __syncthreads();
    if (kHalf == 0) {
        const int bb = z >> 4, hh = z & 15;
        #pragma unroll
        for (int rp = 0; rp < 2; rp++) {
            int row  = lr + rp * 8;
            int colh = nOct * 8 + 2 * lc;
            float ri = rinvs[row];
            float v0 = (acc[rp*2+0] + pacc[nOct * 128 + lane * 4 + rp*2+0]) * ri;
            float v1 = (acc[rp*2+1] + pacc[nOct * 128 + lane * 4 + rp*2+1]) * ri;
            int t = t0 + row;
            *(float2*)&attn_mid[((size_t)(t * BSZ + bb)) * EDIM + hh * 64 + colh]
                = make_float2(v0, v1);
        }
    }
}

// ---------------- launcher ----------------------------------------------------
extern "C" void kernel_launch(void* const* d_in, const int* in_sizes, int n_in,
                              void* d_out, int out_size) {
    const float* query = (const float*)d_in[0];
    const float* key   = (const float*)d_in[1];
    const float* value = (const float*)d_in[2];
    const int*   mask  = (const int*)  d_in[3];
    const float* Wq = (const float*)d_in[4];
    const float* bq = (const float*)d_in[5];
    const float* Wk = (const float*)d_in[6];
    const float* bk = (const float*)d_in[7];
    const float* Wv = (const float*)d_in[8];
    const float* bv = (const float*)d_in[9];
    const float* Wo = (const float*)d_in[10];
    const float* bo = (const float*)d_in[11];

    float *pq, *pk, *pv, *pmid, *psink;
    cudaGetSymbolAddress((void**)&pq,   g_q);
    cudaGetSymbolAddress((void**)&pk,   g_k);
    cudaGetSymbolAddress((void**)&pv,   g_v);
    cudaGetSymbolAddress((void**)&pmid, g_mid);
    cudaGetSymbolAddress((void**)&psink, g_sink);

    const long long ATTN_N = (long long)TDIM * BSZ * EDIM;       // 4,194,304
    const long long WTS_N  = (long long)NZ * TDIM * SDIM;        // 134,217,728
    float* out = (float*)d_out;
    float* out_attn = out;
    float* out_w    = nullptr;
    int write_w = 0;
    long long osz = (long long)out_size;
    if (osz >= ATTN_N + WTS_N)      { out_attn = out; out_w = out + ATTN_N; write_w = 1; }
    else if (osz == WTS_N)          { out_attn = psink; out_w = out; write_w = 1; }
    else                            { out_attn = out; write_w = 0; out_w = psink; }

    cudaFuncSetAttribute(gemm_tf32_kernel,
                         cudaFuncAttributeMaxDynamicSharedMemorySize, GEMM_SMEM);
    cudaFuncSetAttribute(attn_kernel,
                         cudaFuncAttributeMaxDynamicSharedMemorySize, ATTN_SMEM);

    dim3 gg(EDIM / 128, (TDIM * BSZ) / 128);   // (8, 32)
    gemm_tf32_kernel<<<gg, 256, GEMM_SMEM>>>(query, Wq, bq, pq, 0);
    gemm_tf32_kernel<<<gg, 256, GEMM_SMEM>>>(key,   Wk, bk, pk, 1);
    gemm_tf32_kernel<<<gg, 256, GEMM_SMEM>>>(value, Wv, bv, pv, 1);

    attn_kernel<<<dim3(TDIM / 16, NZ), 512, ATTN_SMEM>>>(
        pq, pk, pv, mask, out_w, pmid, write_w);

    gemm_tf32_kernel<<<gg, 256, GEMM_SMEM>>>(pmid, Wo, bo, out_attn, 2);
}